// round 10
// baseline (speedup 1.0000x reference)
#include <cuda_runtime.h>
#include <cstdint>

// ---------------- problem / tiling constants ----------------
#define NN 8192
#define SS 3
#define DD 32
#define KSPLIT 4
#define KPER (NN / KSPLIT)            // 2048 K per item
#define BM 128
#define BK 64
#define SPI (KPER / BK)               // 32 stages per item
#define NMT (NN / BM)                 // 64 M-tiles
#define NITEMS (NMT * SS * KSPLIT)    // 768 work items
#define NSTAGES 5                     // cp.async buffers, lead 4

// smem layout (floats). Rows are 64 floats (256B); 16-granule XOR swizzle
// (g' = g ^ (row&7)) -> conflict-free STS phases and fragment LDS.
#define SROWF 64
#define SA_FLOATS (BM * SROWF)                 // 8192  (32 KB)
#define SB_FLOATS (DD * SROWF)                 // 2048  (8 KB)
#define BBASE (NSTAGES * SA_FLOATS)            // 40960
#define SMEM_FLOATS (BBASE + NSTAGES * SB_FLOATS)   // 51200 -> 204800 B

// ---------------- scratch (no cudaMalloc allowed) ----------------
__device__ float g_preT[SS * DD * NN];            // preT[s][o][n], tf32-rn, 3 MB
__device__ float g_part[SS * KSPLIT][NN * DD];    // K-split partials, 12 MB
__device__ int   g_ctr;                           // work-steal counter

// tf32 round-to-nearest: +0x1000 into bit 12; MMA HW truncates low 13 bits.
__device__ __forceinline__ uint32_t tf32rn(uint32_t u) { return u + 0x1000u; }

// ---------------- cp.async helpers ----------------
__device__ __forceinline__ void cp16(uint32_t saddr, const float* g) {
    asm volatile("cp.async.cg.shared.global [%0], [%1], 16;"
                 :: "r"(saddr), "l"(g) : "memory");
}
__device__ __forceinline__ void cp_commit() {
    asm volatile("cp.async.commit_group;" ::: "memory");
}
__device__ __forceinline__ void cp_wait3() {
    asm volatile("cp.async.wait_group 3;" ::: "memory");
}

// ---------------------------------------------------------------------------
// Kernel 1: preT[s][o][n] = rn_tf32( b[s][o] + sum_i x[n][i]*W[s][i][o] )
// Grid (32, 3), 256 thr; thread owns one n-row (x in regs), 32 outputs.
// Also resets the work-steal counter each replay.
// ---------------------------------------------------------------------------
__global__ __launch_bounds__(256) void pre_kernel(const float* __restrict__ x,
                                                  const float* __restrict__ W,
                                                  const float* __restrict__ b,
                                                  int nworkers) {
    if (blockIdx.x == 0 && blockIdx.y == 0 && threadIdx.x == 0)
        g_ctr = nworkers;

    __shared__ float sx[256 * 33];
    __shared__ float sW[DD * DD];
    __shared__ float sb[DD];

    int s = blockIdx.y, n0 = blockIdx.x * 256;
    int t = threadIdx.x;

    for (int i = t; i < 256 * DD; i += 256) {
        int row = i >> 5, col = i & 31;
        sx[row * 33 + col] = x[(size_t)n0 * DD + i];
    }
    for (int i = t; i < DD * DD; i += 256) sW[i] = W[s * DD * DD + i];
    if (t < DD) sb[t] = b[s * DD + t];
    __syncthreads();

    float xr[DD];
#pragma unroll
    for (int i = 0; i < DD; i++) xr[i] = sx[t * 33 + i];   // bank (t+i)%32, clean

#pragma unroll
    for (int oc = 0; oc < 4; oc++) {
        float acc[8];
#pragma unroll
        for (int j = 0; j < 8; j++) acc[j] = sb[oc * 8 + j];
#pragma unroll
        for (int i = 0; i < DD; i++) {
#pragma unroll
            for (int j = 0; j < 8; j++)
                acc[j] = fmaf(xr[i], sW[i * DD + oc * 8 + j], acc[j]);  // broadcast
        }
#pragma unroll
        for (int j = 0; j < 8; j++)
            g_preT[(size_t)(s * DD + oc * 8 + j) * NN + n0 + t] =
                __uint_as_float(tf32rn(__float_as_uint(acc[j])));
    }
}

// ---------------------------------------------------------------------------
// Kernel 2: persistent work-stealing tf32 mma.sync GEMM.
// 1 CTA/SM, BM=128 (8 warps x m16n32), BK=64 (256B bursts per row),
// 5-buffer cp.async pipeline (lead 4), one barrier per stage, continuous
// across item boundaries.
// ---------------------------------------------------------------------------
__global__ void __launch_bounds__(256, 1) gemm_kernel(const float* __restrict__ adj) {
    extern __shared__ float smem[];
    __shared__ int s_next;
    const uint32_t sbase = (uint32_t)__cvta_generic_to_shared(smem);

    const int t = threadIdx.x;
    const int wid = t >> 5, lane = t & 31;
    const int r = lane >> 2, c = lane & 3;
    const int m0w = wid * 16;

    auto decode = [&](int it, const float*& aB, const float*& bB, int& s, int& z, int& mt) {
        mt = it & (NMT - 1);
        int sz = it >> 6;                 // NMT = 64
        s = sz % SS; z = sz / SS;
        aB = adj + ((size_t)(s * NN + mt * BM)) * NN + (size_t)z * KPER;
        bB = g_preT + (size_t)s * DD * NN + (size_t)z * KPER;
    };

    auto issue = [&](const float* aB, const float* bB, int st, int buf) {
        uint32_t sa = sbase + (buf * SA_FLOATS) * 4;
        uint32_t sb = sbase + (BBASE + buf * SB_FLOATS) * 4;
#pragma unroll
        for (int i = 0; i < 8; i++) {
            int idx = i * 256 + t;        // 2048 granules: 128 rows x 16
            int row = idx >> 4, g = idx & 15;
            int gs = g ^ (row & 7);
            cp16(sa + (row * SROWF + gs * 4) * 4,
                 aB + (size_t)row * NN + st * BK + g * 4);
        }
#pragma unroll
        for (int j = 0; j < 2; j++) {
            int idx = j * 256 + t;        // 512 granules: 32 rows x 16
            int row = idx >> 4, g = idx & 15;
            int gs = g ^ (row & 7);
            cp16(sb + (row * SROWF + gs * 4) * 4,
                 bB + (size_t)row * NN + st * BK + g * 4);
        }
    };

    auto compute = [&](int buf, float (&acc)[4][4]) {
        const uint32_t* sA = reinterpret_cast<const uint32_t*>(smem + buf * SA_FLOATS);
        const uint32_t* sB = reinterpret_cast<const uint32_t*>(smem + BBASE + buf * SB_FLOATS);
#pragma unroll
        for (int k8 = 0; k8 < BK / 8; k8++) {
            int gs0 = (2 * k8) ^ r;       // swizzled granule, cols k0..k0+3
            int gs1 = (2 * k8 + 1) ^ r;   // cols k0+4..k0+7
            uint32_t a0 = tf32rn(sA[(m0w + r) * SROWF + gs0 * 4 + c]);
            uint32_t a1 = tf32rn(sA[(m0w + r + 8) * SROWF + gs0 * 4 + c]);
            uint32_t a2 = tf32rn(sA[(m0w + r) * SROWF + gs1 * 4 + c]);
            uint32_t a3 = tf32rn(sA[(m0w + r + 8) * SROWF + gs1 * 4 + c]);
#pragma unroll
            for (int nt = 0; nt < 4; nt++) {
                uint32_t b0 = sB[(nt * 8 + r) * SROWF + gs0 * 4 + c];
                uint32_t b1 = sB[(nt * 8 + r) * SROWF + gs1 * 4 + c];
                asm volatile(
                    "mma.sync.aligned.m16n8k8.row.col.f32.tf32.tf32.f32 "
                    "{%0,%1,%2,%3}, {%4,%5,%6,%7}, {%8,%9}, {%0,%1,%2,%3};"
                    : "+f"(acc[nt][0]), "+f"(acc[nt][1]),
                      "+f"(acc[nt][2]), "+f"(acc[nt][3])
                    : "r"(a0), "r"(a1), "r"(a2), "r"(a3), "r"(b0), "r"(b1));
            }
        }
    };

    // ---- first item + pipeline priming (lead 4, 5 buffers) ----
    int cur = blockIdx.x;                 // grid <= NITEMS
    const float *aB, *bB; int s, z, mt;
    decode(cur, aB, bB, s, z, mt);
    issue(aB, bB, 0, 0); cp_commit();
    issue(aB, bB, 1, 1); cp_commit();
    issue(aB, bB, 2, 2); cp_commit();
    issue(aB, bB, 3, 3); cp_commit();
    int bi = 4, bc = 0;

    while (true) {
        float acc[4][4];
#pragma unroll
        for (int nt = 0; nt < 4; nt++)
#pragma unroll
            for (int j = 0; j < 4; j++) acc[nt][j] = 0.0f;

        const float *naB = nullptr, *nbB = nullptr;
        int ns = 0, nz = 0, nmt = 0, nxt = NITEMS;

#pragma unroll 1
        for (int st = 0; st < SPI; st++) {
            cp_wait3();                   // group st retired (this thread)
            __syncthreads();              // visible to all; buffer bi is free
            if (st == SPI - 5 && t == 0) s_next = atomicAdd(&g_ctr, 1);
            if (st + 4 < SPI) {
                issue(aB, bB, st + 4, bi);
            } else {
                if (st == SPI - 4) {      // s_next write fenced by this barrier
                    nxt = s_next;
                    if (nxt < NITEMS) decode(nxt, naB, nbB, ns, nz, nmt);
                }
                if (nxt < NITEMS) issue(naB, nbB, st + 4 - SPI, bi);
            }
            cp_commit();                  // exactly one group per iter
            bi++; if (bi == NSTAGES) bi = 0;
            compute(bc, acc);
            bc++; if (bc == NSTAGES) bc = 0;
        }

        // ---- epilogue: deterministic partial store for item `cur` ----
        float* po = g_part[s * KSPLIT + z];
#pragma unroll
        for (int nt = 0; nt < 4; nt++)
#pragma unroll
            for (int h = 0; h < 2; h++) {
                int m = mt * BM + m0w + r + 8 * h;
                float2 v = make_float2(acc[nt][2 * h], acc[nt][2 * h + 1]);
                *reinterpret_cast<float2*>(&po[(size_t)m * DD + nt * 8 + 2 * c]) = v;
            }

        if (nxt >= NITEMS) break;
        cur = nxt; aB = naB; bB = nbB; s = ns; z = nz; mt = nmt;
    }
}

// ---------------------------------------------------------------------------
// Kernel 3: out = relu(sum over 12 partials). 512 x 128 for MLP/balance.
// ---------------------------------------------------------------------------
__global__ __launch_bounds__(128) void reduce_kernel(float* __restrict__ out) {
    int i = blockIdx.x * 128 + threadIdx.x;
    float4 a = make_float4(0.f, 0.f, 0.f, 0.f);
#pragma unroll
    for (int p = 0; p < SS * KSPLIT; p++) {
        float4 v = reinterpret_cast<const float4*>(g_part[p])[i];
        a.x += v.x; a.y += v.y; a.z += v.z; a.w += v.w;
    }
    a.x = fmaxf(a.x, 0.f); a.y = fmaxf(a.y, 0.f);
    a.z = fmaxf(a.z, 0.f); a.w = fmaxf(a.w, 0.f);
    reinterpret_cast<float4*>(out)[i] = a;
}

// ---------------------------------------------------------------------------
// Launch: pre -> persistent gemm (148 CTAs) -> reduce
// ---------------------------------------------------------------------------
extern "C" void kernel_launch(void* const* d_in, const int* in_sizes, int n_in,
                              void* d_out, int out_size) {
    const float* x   = (const float*)d_in[0];   // [8192, 32]
    const float* adj = (const float*)d_in[1];   // [3, 8192, 8192]
    const float* W   = (const float*)d_in[2];   // [3, 32, 32]
    const float* b   = (const float*)d_in[3];   // [3, 32]
    float* out = (float*)d_out;                 // [8192, 32]

    cudaFuncSetAttribute(gemm_kernel, cudaFuncAttributeMaxDynamicSharedMemorySize,
                         SMEM_FLOATS * 4);
    int sms = 148;
    cudaDeviceGetAttribute(&sms, cudaDevAttrMultiProcessorCount, 0);
    int workers = sms;
    if (workers > NITEMS) workers = NITEMS;

    pre_kernel<<<dim3(NN / 256, SS), 256>>>(x, W, b, workers);
    gemm_kernel<<<workers, 256, SMEM_FLOATS * 4>>>(adj);
    reduce_kernel<<<(NN * DD / 4) / 128, 128>>>(out);
}